// round 2
// baseline (speedup 1.0000x reference)
#include <cuda_runtime.h>
#include <math.h>

#define N_NODES 200
#define NM1     199
#define E_TOT   39800
#define NODE_CH 1024

// ---------------- scratch (device globals; no allocation) ----------------
__device__ __align__(16) float g_part[8 * 200 * 512];   // split-K partials
__device__ __align__(16) float g_h1[200 * 512];
__device__ __align__(16) float g_h2[200 * 256];
__device__ __align__(16) float g_x [200 * 1024];
__device__ __align__(16) float g_G [200 * 512];         // [n][h*4+o]
__device__ __align__(16) float g_c [200 * 4];
__device__ __align__(16) float g_msg[E_TOT * 4];
__device__ __align__(16) float g_wp2p[1024 * 512];      // permuted wp2

// ---------------- permute wp2[h,4096] -> Wp2p[i*512 + h*4+o] ----------------
__global__ void permute_wp2_kernel(const float* __restrict__ wp2,
                                   float* __restrict__ outp) {
    int idx = blockIdx.x * blockDim.x + threadIdx.x;
    if (idx >= 1024 * 512) return;
    int i = idx >> 9;
    int r = idx & 511;
    int h = r >> 2, o = r & 3;
    outp[idx] = wp2[h * 4096 + i * 4 + o];
}

// ---------------- generic tiled GEMM with optional split-K ----------------
// C[M,N] = act(A[M,K] @ B[K,N] + bias)   (row-major everywhere)
// nsplit>1: blockIdx.z handles K-chunk, writes raw partial into out
#define BM 16
#define BN 64
#define BK 16
__global__ void gemm_kernel(const float* __restrict__ A,
                            const float* __restrict__ B,
                            const float* __restrict__ bias,
                            float* __restrict__ out,
                            int M, int N, int K, int act, int nsplit) {
    __shared__ float As[BM * BK];
    __shared__ float Bs[BK * BN];
    int t  = threadIdx.x;           // 128 threads
    int tx = t & 15, ty = t >> 4;
    int col0 = blockIdx.x * BN, row0 = blockIdx.y * BM;
    int kc = K / nsplit;
    int k0 = blockIdx.z * kc, k1 = k0 + kc;

    float acc[2][4];
#pragma unroll
    for (int r = 0; r < 2; r++)
#pragma unroll
        for (int q = 0; q < 4; q++) acc[r][q] = 0.f;

    int am = t >> 3;            // 0..15
    int ak = (t & 7) * 2;       // 0..14
    int bk = t >> 3;            // 0..15
    int bn = (t & 7) * 8;       // 0..56

    for (int kt = k0; kt < k1; kt += BK) {
        {   // load A tile
            int gr = row0 + am;
            float v0 = 0.f, v1 = 0.f;
            if (gr < M) {
                v0 = A[gr * K + kt + ak];
                v1 = A[gr * K + kt + ak + 1];
            }
            As[am * BK + ak] = v0;
            As[am * BK + ak + 1] = v1;
        }
        {   // load B tile (vectorized)
            const float4* bp = (const float4*)(B + (size_t)(kt + bk) * N + col0 + bn);
            float4 x0 = bp[0], x1 = bp[1];
            *(float4*)(Bs + bk * BN + bn)     = x0;
            *(float4*)(Bs + bk * BN + bn + 4) = x1;
        }
        __syncthreads();
#pragma unroll
        for (int kk = 0; kk < BK; kk++) {
            float b0 = Bs[kk * BN + tx * 4 + 0];
            float b1 = Bs[kk * BN + tx * 4 + 1];
            float b2 = Bs[kk * BN + tx * 4 + 2];
            float b3 = Bs[kk * BN + tx * 4 + 3];
            float a0 = As[(ty * 2 + 0) * BK + kk];
            float a1 = As[(ty * 2 + 1) * BK + kk];
            acc[0][0] += a0 * b0; acc[0][1] += a0 * b1;
            acc[0][2] += a0 * b2; acc[0][3] += a0 * b3;
            acc[1][0] += a1 * b0; acc[1][1] += a1 * b1;
            acc[1][2] += a1 * b2; acc[1][3] += a1 * b3;
        }
        __syncthreads();
    }

    if (nsplit > 1) {
        float* op = out + (size_t)blockIdx.z * M * N;
#pragma unroll
        for (int r = 0; r < 2; r++) {
            int gr = row0 + ty * 2 + r;
            if (gr < M)
#pragma unroll
                for (int q = 0; q < 4; q++)
                    op[gr * N + col0 + tx * 4 + q] = acc[r][q];
        }
    } else {
#pragma unroll
        for (int r = 0; r < 2; r++) {
            int gr = row0 + ty * 2 + r;
            if (gr < M)
#pragma unroll
                for (int q = 0; q < 4; q++) {
                    float v = acc[r][q];
                    if (bias) v += bias[col0 + tx * 4 + q];
                    if (act == 1) v = fmaxf(v, 0.f);
                    out[gr * N + col0 + tx * 4 + q] = v;
                }
        }
    }
}

__global__ void reduce_bias_act_kernel(const float* __restrict__ part,
                                       const float* __restrict__ bias,
                                       float* __restrict__ out,
                                       int M, int N, int ns, int act) {
    int idx = blockIdx.x * blockDim.x + threadIdx.x;
    if (idx >= M * N) return;
    float s = 0.f;
    for (int z = 0; z < ns; z++) s += part[(size_t)z * M * N + idx];
    if (bias) s += bias[idx % N];
    if (act == 1) s = fmaxf(s, 0.f);
    out[idx] = s;
}

// ---------------- c[n,o] = x@bp2_reshaped ; head = sigmoid(x@wi+bi) ----------------
__global__ void c_head_kernel(const float* __restrict__ x,
                              const float* __restrict__ bp2,
                              const float* __restrict__ wi,
                              const float* __restrict__ bi,
                              float* __restrict__ c,
                              float* __restrict__ out2) {
    int n = blockIdx.x, t = threadIdx.x;
    float a[8];
#pragma unroll
    for (int q = 0; q < 8; q++) a[q] = 0.f;
    for (int k = t; k < NODE_CH; k += 256) {
        float xv = x[n * NODE_CH + k];
#pragma unroll
        for (int o = 0; o < 4; o++) {
            a[o]     += xv * bp2[k * 4 + o];
            a[4 + o] += xv * wi[k * 4 + o];
        }
    }
    __shared__ float red[256 * 8];
#pragma unroll
    for (int q = 0; q < 8; q++) red[t * 8 + q] = a[q];
    __syncthreads();
    for (int s = 128; s > 0; s >>= 1) {
        if (t < s)
#pragma unroll
            for (int q = 0; q < 8; q++) red[t * 8 + q] += red[(t + s) * 8 + q];
        __syncthreads();
    }
    if (t == 0) {
#pragma unroll
        for (int o = 0; o < 4; o++) {
            c[n * 4 + o] = red[o];
            out2[n * 4 + o] = 1.f / (1.f + expf(-(red[4 + o] + bi[o])));
        }
    }
}

// ---------------- fused edge kernel: pair -> MLP -> sigmoid -> heh -> msg ----------------
#define TE 32
__global__ void edge_kernel(const float* __restrict__ bbox,
                            const float* __restrict__ dirs,
                            const float* __restrict__ pri,
                            const float* __restrict__ we1, const float* __restrict__ be1,
                            const float* __restrict__ we2, const float* __restrict__ be2,
                            const float* __restrict__ we3, const float* __restrict__ be3,
                            const float* __restrict__ wp1, const float* __restrict__ bp1,
                            const float* __restrict__ G,  const float* __restrict__ c,
                            float* __restrict__ edge_out, float* __restrict__ msg) {
    __shared__ float s_pair[TE * 16];
    __shared__ float s_h1[TE * 256];   // reused as heh [TE*128] later
    __shared__ float s_h2[TE * 64];    // reused as staged G rows (2x512) later
    __shared__ float s_e4[TE * 4];
    __shared__ int   s_src[TE], s_dst[TE];
    float* s_heh = s_h1;
    float* s_G   = s_h2;

    int t = threadIdx.x;               // 256 threads
    int base = blockIdx.x * TE;

    if (t < TE) {
        int ge = base + t;
        int i = 0, j = 0;
        if (ge < E_TOT) {
            i = ge / NM1;
            int r = ge - i * NM1;
            j = (r < i) ? r : r + 1;
        }
        s_src[t] = i; s_dst[t] = j;
    }
    __syncthreads();

    // build pair features [TE,16]
    for (int idx = t; idx < TE * 16; idx += 256) {
        int e = idx >> 4, k = idx & 15;
        int ge = base + e;
        float v = 0.f;
        if (ge < E_TOT) {
            int node = (k < 8) ? s_src[e] : s_dst[e];
            int kk = k & 7;
            v = (kk < 4) ? bbox[node * 4 + kk] * (1.0f / 1024.0f)
                         : dirs[node * 4 + kk - 4];
        }
        s_pair[idx] = v;
    }
    __syncthreads();

    // layer1: 16 -> 256, relu. thread t owns unit u=t for all TE edges.
    {
        float w[16];
#pragma unroll
        for (int k = 0; k < 16; k++) w[k] = we1[k * 256 + t];
        float b = be1[t];
        for (int e = 0; e < TE; e++) {
            float acc = b;
#pragma unroll
            for (int k = 0; k < 16; k++) acc += s_pair[e * 16 + k] * w[k];
            s_h1[e * 256 + t] = fmaxf(acc, 0.f);
        }
    }
    __syncthreads();

    // layer2: 256 -> 64, relu. thread owns 2 edges x 4 units.
    {
        int vq = t & 15;           // unit group: v = vq*4 .. +3
        int eg = t >> 4;           // 0..15 -> edges eg*2, eg*2+1
        int e0 = eg * 2, e1 = e0 + 1;
        float acc0[4], acc1[4];
#pragma unroll
        for (int q = 0; q < 4; q++) { acc0[q] = be2[vq * 4 + q]; acc1[q] = acc0[q]; }
        for (int u = 0; u < 256; u++) {
            float4 wv = *(const float4*)(we2 + u * 64 + vq * 4);
            float ha = s_h1[e0 * 256 + u];
            float hb = s_h1[e1 * 256 + u];
            acc0[0] += ha * wv.x; acc0[1] += ha * wv.y; acc0[2] += ha * wv.z; acc0[3] += ha * wv.w;
            acc1[0] += hb * wv.x; acc1[1] += hb * wv.y; acc1[2] += hb * wv.z; acc1[3] += hb * wv.w;
        }
        float4 r0 = make_float4(fmaxf(acc0[0],0.f), fmaxf(acc0[1],0.f), fmaxf(acc0[2],0.f), fmaxf(acc0[3],0.f));
        float4 r1 = make_float4(fmaxf(acc1[0],0.f), fmaxf(acc1[1],0.f), fmaxf(acc1[2],0.f), fmaxf(acc1[3],0.f));
        *(float4*)(s_h2 + e0 * 64 + vq * 4) = r0;
        *(float4*)(s_h2 + e1 * 64 + vq * 4) = r1;
    }
    __syncthreads();

    // layer3: 64 -> 3 sigmoid, plus higher_pri channel
    if (t < TE * 3) {
        int e = t / 3, w = t - e * 3;
        float acc = be3[w];
        for (int v = 0; v < 64; v++) acc += s_h2[e * 64 + v] * we3[v * 3 + w];
        float sg = 1.f / (1.f + expf(-acc));
        s_e4[e * 4 + w] = sg;
        int ge = base + e;
        if (ge < E_TOT) edge_out[ge * 4 + w] = sg;
    } else if (t < TE * 4) {
        int e = t - TE * 3;
        int ge = base + e;
        float hp = 0.f;
        if (ge < E_TOT) hp = (pri[s_src[e]] > pri[s_dst[e]]) ? 1.f : 0.f;
        s_e4[e * 4 + 3] = hp;
        if (ge < E_TOT) edge_out[ge * 4 + 3] = hp;
    }
    __syncthreads();   // s_h2 consumed; safe to repurpose below

    // heh = relu(e4 @ wp1 + bp1)  [TE,128]  (overwrites s_h1)
    {
        int h = t & 127, eg = t >> 7;   // eg 0..1
        float w0 = wp1[h], w1v = wp1[128 + h], w2v = wp1[256 + h], w3v = wp1[384 + h];
        float b = bp1[h];
        for (int s = 0; s < 16; s++) {
            int e = eg * 16 + s;
            float acc = b + s_e4[e * 4 + 0] * w0 + s_e4[e * 4 + 1] * w1v
                          + s_e4[e * 4 + 2] * w2v + s_e4[e * 4 + 3] * w3v;
            s_heh[e * 128 + h] = fmaxf(acc, 0.f);
        }
    }
    // stage G rows for the (at most 2) distinct src nodes of this block
    {
        int src0 = s_src[0];
        int src1 = s_src[TE - 1];
        for (int idx = t; idx < 1024; idx += 256) {
            int row = idx >> 9;                     // 0 or 1
            int k = idx & 511;
            int src = row ? src1 : src0;
            s_G[idx] = G[src * 512 + k];
        }
    }
    __syncthreads();

    // msg[e,o] = sum_h heh[e,h] * G[src, h*4+o] + c[src,o]
    if (t < TE * 4) {
        int e = t >> 2, o = t & 3;
        int ge = base + e;
        if (ge < E_TOT) {
            int src = s_src[e];
            int roff = (src == s_src[0]) ? 0 : 512;
            float acc = c[src * 4 + o];
            const float* Gp = s_G + roff + o;
#pragma unroll 8
            for (int h = 0; h < 128; h++) acc += s_heh[e * 128 + h] * Gp[h * 4];
            msg[ge * 4 + o] = acc;
        }
    }
}

// ---------------- final: agg over dst + root linear ----------------
__global__ void final_kernel(const float* __restrict__ msg,
                             const float* __restrict__ x,
                             const float* __restrict__ rw,
                             const float* __restrict__ rb,
                             float* __restrict__ out) {
    int j = blockIdx.x, t = threadIdx.x;
    float a[4] = {0.f, 0.f, 0.f, 0.f};
    if (t < N_NODES && t != j) {
        int i = t;
        int pos = (j < i) ? j : j - 1;
        int e = i * NM1 + pos;
        float4 m = *(const float4*)(msg + e * 4);
        a[0] = m.x; a[1] = m.y; a[2] = m.z; a[3] = m.w;
    }
    for (int k = t; k < NODE_CH; k += 256) {
        float xv = x[j * NODE_CH + k];
#pragma unroll
        for (int o = 0; o < 4; o++) a[o] += xv * rw[k * 4 + o];
    }
    __shared__ float red[256 * 4];
#pragma unroll
    for (int q = 0; q < 4; q++) red[t * 4 + q] = a[q];
    __syncthreads();
    for (int s = 128; s > 0; s >>= 1) {
        if (t < s)
#pragma unroll
            for (int q = 0; q < 4; q++) red[t * 4 + q] += red[(t + s) * 4 + q];
        __syncthreads();
    }
    if (t < 4) out[j * 4 + t] = red[t] + rb[t];
}

// ---------------- launcher ----------------
extern "C" void kernel_launch(void* const* d_in, const int* in_sizes, int n_in,
                              void* d_out, int out_size) {
    const float* roi   = (const float*)d_in[0];   // [2,200,2048] (batch0 first)
    const float* bbox  = (const float*)d_in[1];   // [2,200,4]
    const float* dirs  = (const float*)d_in[2];   // [2,200,4]
    const float* pri   = (const float*)d_in[3];   // [2,200]
    const float* w1    = (const float*)d_in[4];
    const float* b1    = (const float*)d_in[5];
    const float* w2    = (const float*)d_in[6];
    const float* b2    = (const float*)d_in[7];
    const float* w3    = (const float*)d_in[8];
    const float* b3    = (const float*)d_in[9];
    const float* wi    = (const float*)d_in[10];
    const float* bi    = (const float*)d_in[11];
    const float* we1   = (const float*)d_in[12];
    const float* be1   = (const float*)d_in[13];
    const float* we2   = (const float*)d_in[14];
    const float* be2   = (const float*)d_in[15];
    const float* we3   = (const float*)d_in[16];
    const float* be3   = (const float*)d_in[17];
    const float* wp1   = (const float*)d_in[18];
    const float* bp1   = (const float*)d_in[19];
    const float* wp2   = (const float*)d_in[20];
    const float* bp2   = (const float*)d_in[21];
    const float* rootw = (const float*)d_in[22];
    const float* rootb = (const float*)d_in[23];
    float* out = (float*)d_out;  // [800 next_actions][800 concepts][159200 edge_attr]

    float *pPart, *pH1, *pH2, *pX, *pG, *pC, *pMsg, *pWp2p;
    cudaGetSymbolAddress((void**)&pPart, g_part);
    cudaGetSymbolAddress((void**)&pH1,   g_h1);
    cudaGetSymbolAddress((void**)&pH2,   g_h2);
    cudaGetSymbolAddress((void**)&pX,    g_x);
    cudaGetSymbolAddress((void**)&pG,    g_G);
    cudaGetSymbolAddress((void**)&pC,    g_c);
    cudaGetSymbolAddress((void**)&pMsg,  g_msg);
    cudaGetSymbolAddress((void**)&pWp2p, g_wp2p);

    // permute wp2 for the reassociated NNConv
    permute_wp2_kernel<<<(1024 * 512 + 255) / 256, 256>>>(wp2, pWp2p);

    int mblk = (N_NODES + BM - 1) / BM;   // 13

    // node MLP layer1: [200,2048]@[2048,512] relu, split-K=8
    {
        dim3 g(512 / BN, mblk, 8);
        gemm_kernel<<<g, 128>>>(roi, w1, nullptr, pPart, N_NODES, 512, 2048, 0, 8);
        reduce_bias_act_kernel<<<(N_NODES * 512 + 255) / 256, 256>>>(pPart, b1, pH1, N_NODES, 512, 8, 1);
    }
    // layer2: [200,512]@[512,256] relu, split-K=4
    {
        dim3 g(256 / BN, mblk, 4);
        gemm_kernel<<<g, 128>>>(pH1, w2, nullptr, pPart, N_NODES, 256, 512, 0, 4);
        reduce_bias_act_kernel<<<(N_NODES * 256 + 255) / 256, 256>>>(pPart, b2, pH2, N_NODES, 256, 4, 1);
    }
    // layer3: [200,256]@[256,1024] + b3 (no act), direct
    {
        dim3 g(1024 / BN, mblk, 1);
        gemm_kernel<<<g, 128>>>(pH2, w3, b3, pX, N_NODES, 1024, 256, 0, 1);
    }
    // G = x @ Wp2p : [200,1024]@[1024,512], split-K=4, no bias/act
    {
        dim3 g(512 / BN, mblk, 4);
        gemm_kernel<<<g, 128>>>(pX, pWp2p, nullptr, pPart, N_NODES, 512, 1024, 0, 4);
        reduce_bias_act_kernel<<<(N_NODES * 512 + 255) / 256, 256>>>(pPart, nullptr, pG, N_NODES, 512, 4, 0);
    }
    // c + sigmoid concept head (writes out[800..1600))
    c_head_kernel<<<N_NODES, 256>>>(pX, bp2, wi, bi, pC, out + 800);

    // fused edge MLP + heh + msg (writes out[1600..) edge attrs)
    edge_kernel<<<(E_TOT + TE - 1) / TE, 256>>>(bbox, dirs, pri,
                                                we1, be1, we2, be2, we3, be3,
                                                wp1, bp1, pG, pC,
                                                out + 1600, pMsg);

    // aggregation + root linear (writes out[0..800))
    final_kernel<<<N_NODES, 256>>>(pMsg, pX, rootw, rootb, out);
}

// round 3
// speedup vs baseline: 1.0264x; 1.0264x over previous
#include <cuda_runtime.h>
#include <math.h>

#define N_NODES 200
#define NM1     199
#define E_TOT   39800
#define NODE_CH 1024

typedef unsigned long long u64;

__device__ __forceinline__ u64 pack2(float lo, float hi) {
    u64 r; asm("mov.b64 %0,{%1,%2};" : "=l"(r) : "f"(lo), "f"(hi)); return r;
}
__device__ __forceinline__ void unpack2(u64 v, float& lo, float& hi) {
    asm("mov.b64 {%0,%1},%2;" : "=f"(lo), "=f"(hi) : "l"(v));
}
__device__ __forceinline__ void ffma2(u64& d, u64 a, u64 b) {
    asm("fma.rn.f32x2 %0,%1,%2,%0;" : "+l"(d) : "l"(a), "l"(b));
}

// ---------------- scratch (device globals; no allocation) ----------------
__device__ __align__(16) float g_part[16 * 200 * 512];  // split-K partials
__device__ __align__(16) float g_h1[200 * 512];
__device__ __align__(16) float g_h2[200 * 256];
__device__ __align__(16) float g_x [200 * 1024];
__device__ __align__(16) float g_G [200 * 512];         // [n][h*4+o]
__device__ __align__(16) float g_c [200 * 4];
__device__ __align__(16) float g_msg[E_TOT * 4];
__device__ __align__(16) float g_wp2p[1024 * 512];      // permuted wp2
__device__ __align__(16) float g_A [200 * 256];         // attr@we1[0:8]+be1
__device__ __align__(16) float g_B [200 * 256];         // attr@we1[8:16]

// ---------------- permute wp2[h,4096] -> Wp2p[i*512 + h*4+o] ----------------
__global__ void permute_wp2_kernel(const float* __restrict__ wp2,
                                   float* __restrict__ outp) {
    int idx = blockIdx.x * blockDim.x + threadIdx.x;
    if (idx >= 1024 * 512) return;
    int i = idx >> 9;
    int r = idx & 511;
    int h = r >> 2, o = r & 3;
    outp[idx] = wp2[h * 4096 + i * 4 + o];
}

// ---------------- per-node separable edge-layer1 precompute ----------------
__global__ void prep_kernel(const float* __restrict__ bbox,
                            const float* __restrict__ dirs,
                            const float* __restrict__ we1,
                            const float* __restrict__ be1,
                            float* __restrict__ Ag, float* __restrict__ Bg) {
    int n = blockIdx.x, u = threadIdx.x;   // 256 threads
    float attr[8];
#pragma unroll
    for (int k = 0; k < 4; k++) attr[k] = bbox[n * 4 + k] * (1.0f / 1024.0f);
#pragma unroll
    for (int k = 0; k < 4; k++) attr[4 + k] = dirs[n * 4 + k];
    float a = be1[u], b = 0.f;
#pragma unroll
    for (int k = 0; k < 8; k++) {
        a += attr[k] * we1[k * 256 + u];
        b += attr[k] * we1[(8 + k) * 256 + u];
    }
    Ag[n * 256 + u] = a;
    Bg[n * 256 + u] = b;
}

// ---------------- tiled split-K GEMM with f32x2 ----------------
#define BM 16
#define BN 64
#define BK 16
__global__ void __launch_bounds__(128)
gemm_kernel(const float* __restrict__ A, const float* __restrict__ B,
            const float* __restrict__ bias, float* __restrict__ out,
            int M, int N, int K, int act, int nsplit) {
    __shared__ __align__(16) float As[BK * BM];   // [k][m]
    __shared__ __align__(16) float Bs[BK * BN];
    int t = threadIdx.x;
    int tx = t & 15, ty = t >> 4;                 // ty: row-pair 0..7
    int col0 = blockIdx.x * BN, row0 = blockIdx.y * BM;
    int kc = K / nsplit;
    int k0 = blockIdx.z * kc, k1 = k0 + kc;

    u64 acc[4];
#pragma unroll
    for (int c = 0; c < 4; c++) acc[c] = pack2(0.f, 0.f);

    int am = t >> 3;            // 0..15 (m)
    int ak = (t & 7) * 2;       // 0..14 (k)
    int bk = t >> 3;
    int bn = (t & 7) * 8;
    unsigned sa = (unsigned)__cvta_generic_to_shared(As + ty * 2);

    for (int kt = k0; kt < k1; kt += BK) {
        {
            int gr = row0 + am;
            float2 av = make_float2(0.f, 0.f);
            if (gr < M) av = *(const float2*)(A + (size_t)gr * K + kt + ak);
            As[ak * BM + am] = av.x;
            As[(ak + 1) * BM + am] = av.y;
        }
        {
            const float4* bp = (const float4*)(B + (size_t)(kt + bk) * N + col0 + bn);
            *(float4*)(Bs + bk * BN + bn)     = bp[0];
            *(float4*)(Bs + bk * BN + bn + 4) = bp[1];
        }
        __syncthreads();
#pragma unroll
        for (int kk = 0; kk < BK; kk++) {
            u64 ap;
            asm("ld.shared.u64 %0,[%1];" : "=l"(ap) : "r"(sa + kk * (BM * 4)));
            float4 b4 = *(float4*)(Bs + kk * BN + tx * 4);
            ffma2(acc[0], ap, pack2(b4.x, b4.x));
            ffma2(acc[1], ap, pack2(b4.y, b4.y));
            ffma2(acc[2], ap, pack2(b4.z, b4.z));
            ffma2(acc[3], ap, pack2(b4.w, b4.w));
        }
        __syncthreads();
    }

    int gr0 = row0 + ty * 2, gr1 = gr0 + 1;
    if (nsplit > 1) {
        float* op = out + (size_t)blockIdx.z * M * N;
#pragma unroll
        for (int c = 0; c < 4; c++) {
            float lo, hi; unpack2(acc[c], lo, hi);
            if (gr0 < M) op[gr0 * N + col0 + tx * 4 + c] = lo;
            if (gr1 < M) op[gr1 * N + col0 + tx * 4 + c] = hi;
        }
    } else {
#pragma unroll
        for (int c = 0; c < 4; c++) {
            float lo, hi; unpack2(acc[c], lo, hi);
            float bv = bias ? bias[col0 + tx * 4 + c] : 0.f;
            lo += bv; hi += bv;
            if (act == 1) { lo = fmaxf(lo, 0.f); hi = fmaxf(hi, 0.f); }
            if (gr0 < M) out[gr0 * N + col0 + tx * 4 + c] = lo;
            if (gr1 < M) out[gr1 * N + col0 + tx * 4 + c] = hi;
        }
    }
}

__global__ void reduce_bias_act_kernel(const float* __restrict__ part,
                                       const float* __restrict__ bias,
                                       float* __restrict__ out,
                                       int M, int N, int ns, int act) {
    int idx = blockIdx.x * blockDim.x + threadIdx.x;
    if (idx >= M * N) return;
    float s = 0.f;
    for (int z = 0; z < ns; z++) s += part[(size_t)z * M * N + idx];
    if (bias) s += bias[idx % N];
    if (act == 1) s = fmaxf(s, 0.f);
    out[idx] = s;
}

// ---------------- c[n,o] = x@bp2_reshaped ; head = sigmoid(x@wi+bi) ----------------
__global__ void c_head_kernel(const float* __restrict__ x,
                              const float* __restrict__ bp2,
                              const float* __restrict__ wi,
                              const float* __restrict__ bi,
                              float* __restrict__ c,
                              float* __restrict__ out2) {
    int n = blockIdx.x, t = threadIdx.x;
    float a[8];
#pragma unroll
    for (int q = 0; q < 8; q++) a[q] = 0.f;
    for (int k = t; k < NODE_CH; k += 256) {
        float xv = x[n * NODE_CH + k];
#pragma unroll
        for (int o = 0; o < 4; o++) {
            a[o]     += xv * bp2[k * 4 + o];
            a[4 + o] += xv * wi[k * 4 + o];
        }
    }
    __shared__ float red[256 * 8];
#pragma unroll
    for (int q = 0; q < 8; q++) red[t * 8 + q] = a[q];
    __syncthreads();
    for (int s = 128; s > 0; s >>= 1) {
        if (t < s)
#pragma unroll
            for (int q = 0; q < 8; q++) red[t * 8 + q] += red[(t + s) * 8 + q];
        __syncthreads();
    }
    if (t == 0) {
#pragma unroll
        for (int o = 0; o < 4; o++) {
            c[n * 4 + o] = red[o];
            out2[n * 4 + o] = 1.f / (1.f + expf(-(red[4 + o] + bi[o])));
        }
    }
}

// ---------------- fused edge kernel (64 edges / block) ----------------
// phases: h1 (separable) -> layer2 f32x2 GEMM -> layer3+sigmoid -> heh -> msg
__global__ void __launch_bounds__(256)
edge_kernel(const float* __restrict__ Ag, const float* __restrict__ Bg,
            const float* __restrict__ pri,
            const float* __restrict__ we2, const float* __restrict__ be2,
            const float* __restrict__ we3, const float* __restrict__ be3,
            const float* __restrict__ wp1, const float* __restrict__ bp1,
            const float* __restrict__ G,  const float* __restrict__ c,
            float* __restrict__ edge_out, float* __restrict__ msg) {
    // sbuf: [0,4352) h1 chunk [j][68]  -> later h2 flat [e*64+v] -> later heh [e*129+h]
    //       [4352,8448) we2 chunk [j][64] -> later heh tail
    __shared__ __align__(16) float sbuf[8448];
    __shared__ float s_G[1024];
    __shared__ float s_e4[256];
    __shared__ float s_A[512];
    __shared__ int s_src[64], s_dst[64];

    int t = threadIdx.x;
    int base = blockIdx.x * 64;
    int src0 = base / NM1;
    int last = min(base + 63, E_TOT - 1);
    int src1 = last / NM1;

    if (t < 64) {
        int ge = base + t;
        int i = src0, j = 0;
        if (ge < E_TOT) {
            i = ge / NM1;
            int r = ge - i * NM1;
            j = (r < i) ? r : r + 1;
        }
        s_src[t] = i; s_dst[t] = j;
    }
    for (int idx = t; idx < 512; idx += 256) {
        int row = idx >> 8, k = idx & 255;
        s_A[idx] = Ag[(row ? src1 : src0) * 256 + k];
    }
    __syncthreads();

    // ---- layer2: [64e,256u] @ [256u,64v], K in 4 chunks of 64 ----
    int e0 = (t >> 4) * 4;       // 4 edges
    int v0 = (t & 15) * 4;       // 4 outputs
    u64 acc01[4], acc23[4];
#pragma unroll
    for (int cq = 0; cq < 4; cq++) {
        float b = be2[v0 + cq];
        acc01[cq] = pack2(b, b);
        acc23[cq] = pack2(b, b);
    }
    unsigned h1base = (unsigned)__cvta_generic_to_shared(sbuf + e0);

    for (int uc = 0; uc < 4; uc++) {
        // build h1 chunk [j][e], pad 68
        for (int idx = t; idx < 4096; idx += 256) {
            int e = idx >> 6, jj = idx & 63;
            int u = uc * 64 + jj;
            float val = 0.f;
            int ge = base + e;
            if (ge < E_TOT) {
                int aoff = (s_src[e] == src0) ? 0 : 256;
                val = fmaxf(s_A[aoff + u] + Bg[s_dst[e] * 256 + u], 0.f);
            }
            sbuf[jj * 68 + e] = val;
        }
        // load we2 chunk [j][v]
        for (int idx = t; idx < 4096; idx += 256) {
            int jj = idx >> 6, v = idx & 63;
            sbuf[4352 + jj * 64 + v] = we2[(uc * 64 + jj) * 64 + v];
        }
        __syncthreads();
#pragma unroll 8
        for (int jj = 0; jj < 64; jj++) {
            u64 h01, h23;
            asm("ld.shared.v2.u64 {%0,%1},[%2];"
                : "=l"(h01), "=l"(h23) : "r"(h1base + jj * 272));
            float4 w4 = *(float4*)(sbuf + 4352 + jj * 64 + v0);
            u64 wx = pack2(w4.x, w4.x), wy = pack2(w4.y, w4.y);
            u64 wz = pack2(w4.z, w4.z), ww = pack2(w4.w, w4.w);
            ffma2(acc01[0], h01, wx); ffma2(acc23[0], h23, wx);
            ffma2(acc01[1], h01, wy); ffma2(acc23[1], h23, wy);
            ffma2(acc01[2], h01, wz); ffma2(acc23[2], h23, wz);
            ffma2(acc01[3], h01, ww); ffma2(acc23[3], h23, ww);
        }
        __syncthreads();
    }

    // write h2 = relu(acc) into region0 flat [e*64+v]
#pragma unroll
    for (int cq = 0; cq < 4; cq++) {
        float lo, hi;
        unpack2(acc01[cq], lo, hi);
        sbuf[(e0 + 0) * 64 + v0 + cq] = fmaxf(lo, 0.f);
        sbuf[(e0 + 1) * 64 + v0 + cq] = fmaxf(hi, 0.f);
        unpack2(acc23[cq], lo, hi);
        sbuf[(e0 + 2) * 64 + v0 + cq] = fmaxf(lo, 0.f);
        sbuf[(e0 + 3) * 64 + v0 + cq] = fmaxf(hi, 0.f);
    }
    __syncthreads();

    // ---- layer3: 64 -> 3 sigmoid + higher_pri ----
    if (t < 192) {
        int e = t / 3, w = t - e * 3;
        float a = be3[w];
        for (int v = 0; v < 64; v++) a += sbuf[e * 64 + v] * we3[v * 3 + w];
        float sg = 1.f / (1.f + expf(-a));
        s_e4[e * 4 + w] = sg;
        int ge = base + e;
        if (ge < E_TOT) edge_out[ge * 4 + w] = sg;
    } else {
        int e = t - 192;
        int ge = base + e;
        float hp = 0.f;
        if (ge < E_TOT) hp = (pri[s_src[e]] > pri[s_dst[e]]) ? 1.f : 0.f;
        s_e4[e * 4 + 3] = hp;
        if (ge < E_TOT) edge_out[ge * 4 + 3] = hp;
    }
    __syncthreads();

    // ---- heh = relu(e4 @ wp1 + bp1) into sbuf[e*129+h]; stage G rows ----
    {
        int h = t & 127, eg = t >> 7;
        float w0 = wp1[h], w1v = wp1[128 + h], w2v = wp1[256 + h], w3v = wp1[384 + h];
        float b = bp1[h];
#pragma unroll 4
        for (int s = 0; s < 32; s++) {
            int e = eg * 32 + s;
            float a = b + s_e4[e * 4 + 0] * w0 + s_e4[e * 4 + 1] * w1v
                        + s_e4[e * 4 + 2] * w2v + s_e4[e * 4 + 3] * w3v;
            sbuf[e * 129 + h] = fmaxf(a, 0.f);
        }
    }
    for (int idx = t; idx < 1024; idx += 256)
        s_G[idx] = G[((idx < 512) ? src0 : src1) * 512 + (idx & 511)];
    __syncthreads();

    // ---- msg[e,o] = sum_h heh[e,h] * G[src,h*4+o] + c[src,o] ----
    {
        int e = t >> 2, o = t & 3;
        int ge = base + e;
        if (ge < E_TOT) {
            int src = s_src[e];
            int roff = (src == src0) ? 0 : 512;
            float a = c[src * 4 + o];
            const float* hp = sbuf + e * 129;
            const float* gp = s_G + roff + o;
#pragma unroll 8
            for (int h = 0; h < 128; h++) a += hp[h] * gp[h * 4];
            msg[ge * 4 + o] = a;
        }
    }
}

// ---------------- final: agg over dst + root linear ----------------
__global__ void final_kernel(const float* __restrict__ msg,
                             const float* __restrict__ x,
                             const float* __restrict__ rw,
                             const float* __restrict__ rb,
                             float* __restrict__ out) {
    int j = blockIdx.x, t = threadIdx.x;
    float a[4] = {0.f, 0.f, 0.f, 0.f};
    if (t < N_NODES && t != j) {
        int i = t;
        int pos = (j < i) ? j : j - 1;
        int e = i * NM1 + pos;
        float4 m = *(const float4*)(msg + e * 4);
        a[0] = m.x; a[1] = m.y; a[2] = m.z; a[3] = m.w;
    }
    for (int k = t; k < NODE_CH; k += 256) {
        float xv = x[j * NODE_CH + k];
#pragma unroll
        for (int o = 0; o < 4; o++) a[o] += xv * rw[k * 4 + o];
    }
    __shared__ float red[256 * 4];
#pragma unroll
    for (int q = 0; q < 4; q++) red[t * 4 + q] = a[q];
    __syncthreads();
    for (int s = 128; s > 0; s >>= 1) {
        if (t < s)
#pragma unroll
            for (int q = 0; q < 4; q++) red[t * 4 + q] += red[(t + s) * 4 + q];
        __syncthreads();
    }
    if (t < 4) out[j * 4 + t] = red[t] + rb[t];
}

// ---------------- launcher ----------------
extern "C" void kernel_launch(void* const* d_in, const int* in_sizes, int n_in,
                              void* d_out, int out_size) {
    const float* roi   = (const float*)d_in[0];
    const float* bbox  = (const float*)d_in[1];
    const float* dirs  = (const float*)d_in[2];
    const float* pri   = (const float*)d_in[3];
    const float* w1    = (const float*)d_in[4];
    const float* b1    = (const float*)d_in[5];
    const float* w2    = (const float*)d_in[6];
    const float* b2    = (const float*)d_in[7];
    const float* w3    = (const float*)d_in[8];
    const float* b3    = (const float*)d_in[9];
    const float* wi    = (const float*)d_in[10];
    const float* bi    = (const float*)d_in[11];
    const float* we1   = (const float*)d_in[12];
    const float* be1   = (const float*)d_in[13];
    const float* we2   = (const float*)d_in[14];
    const float* be2   = (const float*)d_in[15];
    const float* we3   = (const float*)d_in[16];
    const float* be3   = (const float*)d_in[17];
    const float* wp1   = (const float*)d_in[18];
    const float* bp1   = (const float*)d_in[19];
    const float* wp2   = (const float*)d_in[20];
    const float* bp2   = (const float*)d_in[21];
    const float* rootw = (const float*)d_in[22];
    const float* rootb = (const float*)d_in[23];
    float* out = (float*)d_out;

    float *pPart, *pH1, *pH2, *pX, *pG, *pC, *pMsg, *pWp2p, *pA, *pB;
    cudaGetSymbolAddress((void**)&pPart, g_part);
    cudaGetSymbolAddress((void**)&pH1,   g_h1);
    cudaGetSymbolAddress((void**)&pH2,   g_h2);
    cudaGetSymbolAddress((void**)&pX,    g_x);
    cudaGetSymbolAddress((void**)&pG,    g_G);
    cudaGetSymbolAddress((void**)&pC,    g_c);
    cudaGetSymbolAddress((void**)&pMsg,  g_msg);
    cudaGetSymbolAddress((void**)&pWp2p, g_wp2p);
    cudaGetSymbolAddress((void**)&pA,    g_A);
    cudaGetSymbolAddress((void**)&pB,    g_B);

    permute_wp2_kernel<<<(1024 * 512 + 255) / 256, 256>>>(wp2, pWp2p);
    prep_kernel<<<N_NODES, 256>>>(bbox, dirs, we1, be1, pA, pB);

    int mblk = (N_NODES + BM - 1) / BM;   // 13

    // layer1: [200,2048]@[2048,512], split-K=16
    {
        dim3 g(512 / BN, mblk, 16);
        gemm_kernel<<<g, 128>>>(roi, w1, nullptr, pPart, N_NODES, 512, 2048, 0, 16);
        reduce_bias_act_kernel<<<(N_NODES * 512 + 255) / 256, 256>>>(pPart, b1, pH1, N_NODES, 512, 16, 1);
    }
    // layer2: [200,512]@[512,256], split-K=8
    {
        dim3 g(256 / BN, mblk, 8);
        gemm_kernel<<<g, 128>>>(pH1, w2, nullptr, pPart, N_NODES, 256, 512, 0, 8);
        reduce_bias_act_kernel<<<(N_NODES * 256 + 255) / 256, 256>>>(pPart, b2, pH2, N_NODES, 256, 8, 1);
    }
    // layer3: [200,256]@[256,1024], split-K=4
    {
        dim3 g(1024 / BN, mblk, 4);
        gemm_kernel<<<g, 128>>>(pH2, w3, nullptr, pPart, N_NODES, 1024, 256, 0, 4);
        reduce_bias_act_kernel<<<(N_NODES * 1024 + 255) / 256, 256>>>(pPart, b3, pX, N_NODES, 1024, 4, 0);
    }
    // G = x @ Wp2p : [200,1024]@[1024,512], split-K=8
    {
        dim3 g(512 / BN, mblk, 8);
        gemm_kernel<<<g, 128>>>(pX, pWp2p, nullptr, pPart, N_NODES, 512, 1024, 0, 8);
        reduce_bias_act_kernel<<<(N_NODES * 512 + 255) / 256, 256>>>(pPart, nullptr, pG, N_NODES, 512, 8, 0);
    }
    c_head_kernel<<<N_NODES, 256>>>(pX, bp2, wi, bi, pC, out + 800);

    edge_kernel<<<(E_TOT + 63) / 64, 256>>>(pA, pB, pri,
                                            we2, be2, we3, be3,
                                            wp1, bp1, pG, pC,
                                            out + 1600, pMsg);

    final_kernel<<<N_NODES, 256>>>(pMsg, pX, rootw, rootb, out);
}